// round 1
// baseline (speedup 1.0000x reference)
#include <cuda_runtime.h>
#include <math.h>

// Problem constants (fixed shapes)
#define BB   2
#define SS   2048
#define HIDN 2048
#define HH   8
#define HDD  256

// Scratch (allocation-free rule: __device__ globals)
__device__ float g_q[(size_t)BB*HH*SS*HDD];   // (B,H,S,HD)
__device__ float g_k[(size_t)BB*SS*HDD];      // (B,S,HD)
__device__ float g_v[(size_t)BB*SS*HDD];      // (B,S,HD)
__device__ float g_ctx[(size_t)BB*SS*HIDN];   // (B,S,H*HD)

// ---------------------------------------------------------------------------
// Generic 128x128x8 SGEMM, 256 threads, 8x8 per-thread tile.
// MODE 0: C = A@B        (row-major, ldc=N)            [k,v proj; ctx@Wo]
// MODE 1: q proj scatter: C[(b*H+h)*S+s][d] layout
// MODE 2: scores = scale * q @ k^T, batched over z=(b,h), causal block skip
// MODE 3: ctx = attn @ v, batched over z=(b,h), K-loop truncated at m0+128,
//         scatter to (B,S,H*HD)
// ---------------------------------------------------------------------------
template<int MODE>
__global__ __launch_bounds__(256) void gemm_k(const float* __restrict__ Ag,
                                              const float* __restrict__ Bg,
                                              float* __restrict__ Cg,
                                              int M, int N, int K)
{
    __shared__ float As[8][128];
    __shared__ float Bs[8][128];

    const int tid = threadIdx.x;
    const int tx  = tid & 15;   // 0..15  (n)
    const int ty  = tid >> 4;   // 0..15  (m)
    const int m0  = blockIdx.y * 128;
    const int n0  = blockIdx.x * 128;
    const int z   = blockIdx.z;

    if (MODE == 2 && blockIdx.x > blockIdx.y) return;  // fully-masked tile

    const float* A;
    const float* B;
    int lda, ldb, Kloop;
    if (MODE == 2) {
        A = Ag + (size_t)z * SS * HDD;        lda = HDD;
        B = Bg + (size_t)(z >> 3) * SS * HDD; ldb = HDD;   // k, NT access
        Kloop = HDD;
    } else if (MODE == 3) {
        A = Ag + (size_t)z * SS * SS;         lda = SS;
        B = Bg + (size_t)(z >> 3) * SS * HDD; ldb = HDD;
        Kloop = m0 + 128;                     // attn[t>s]==0 exactly
    } else {
        A = Ag; lda = K; B = Bg; ldb = N; Kloop = K;
    }

    const int aRow = tid >> 1;          // 0..127
    const int aCol = (tid & 1) * 4;     // 0 / 4
    const int bRow = tid >> 5;          // 0..7   (NN load)
    const int bCol = (tid & 31) * 4;    // 0..124
    const int btN  = tid >> 1;          // 0..127 (NT load)
    const int btK  = (tid & 1) * 4;

    float acc[8][8];
    #pragma unroll
    for (int i = 0; i < 8; i++)
        #pragma unroll
        for (int j = 0; j < 8; j++) acc[i][j] = 0.f;

    for (int k0 = 0; k0 < Kloop; k0 += 8) {
        float4 av = *(const float4*)&A[(size_t)(m0 + aRow) * lda + k0 + aCol];
        As[aCol + 0][aRow] = av.x;
        As[aCol + 1][aRow] = av.y;
        As[aCol + 2][aRow] = av.z;
        As[aCol + 3][aRow] = av.w;

        if (MODE == 2) {
            float4 bv = *(const float4*)&B[(size_t)(n0 + btN) * ldb + k0 + btK];
            Bs[btK + 0][btN] = bv.x;
            Bs[btK + 1][btN] = bv.y;
            Bs[btK + 2][btN] = bv.z;
            Bs[btK + 3][btN] = bv.w;
        } else {
            float4 bv = *(const float4*)&B[(size_t)(k0 + bRow) * ldb + n0 + bCol];
            *(float4*)&Bs[bRow][bCol] = bv;
        }
        __syncthreads();

        #pragma unroll
        for (int kk = 0; kk < 8; kk++) {
            float a[8], b[8];
            float4 a0 = *(const float4*)&As[kk][ty * 8];
            float4 a1 = *(const float4*)&As[kk][ty * 8 + 4];
            float4 b0 = *(const float4*)&Bs[kk][tx * 8];
            float4 b1 = *(const float4*)&Bs[kk][tx * 8 + 4];
            a[0]=a0.x; a[1]=a0.y; a[2]=a0.z; a[3]=a0.w;
            a[4]=a1.x; a[5]=a1.y; a[6]=a1.z; a[7]=a1.w;
            b[0]=b0.x; b[1]=b0.y; b[2]=b0.z; b[3]=b0.w;
            b[4]=b1.x; b[5]=b1.y; b[6]=b1.z; b[7]=b1.w;
            #pragma unroll
            for (int i = 0; i < 8; i++)
                #pragma unroll
                for (int j = 0; j < 8; j++)
                    acc[i][j] = fmaf(a[i], b[j], acc[i][j]);
        }
        __syncthreads();
    }

    #pragma unroll
    for (int i = 0; i < 8; i++) {
        int m = m0 + ty * 8 + i;
        int n = n0 + tx * 8;
        float4 v0 = make_float4(acc[i][0], acc[i][1], acc[i][2], acc[i][3]);
        float4 v1 = make_float4(acc[i][4], acc[i][5], acc[i][6], acc[i][7]);
        if (MODE == 0) {
            float* p = Cg + (size_t)m * N + n;
            *(float4*)p = v0; *(float4*)(p + 4) = v1;
        } else if (MODE == 1) {
            int b = m >> 11, s = m & (SS - 1);
            int h = n >> 8, d = n & (HDD - 1);
            float* p = Cg + (((size_t)(b * HH + h) * SS + s) * HDD) + d;
            *(float4*)p = v0; *(float4*)(p + 4) = v1;
        } else if (MODE == 2) {
            const float sc = 0.0625f;  // HD^-0.5
            v0.x *= sc; v0.y *= sc; v0.z *= sc; v0.w *= sc;
            v1.x *= sc; v1.y *= sc; v1.z *= sc; v1.w *= sc;
            float* p = Cg + (size_t)z * SS * SS + (size_t)m * SS + n;
            *(float4*)p = v0; *(float4*)(p + 4) = v1;
        } else {  // MODE 3
            int b = z >> 3, h = z & 7;
            float* p = Cg + ((size_t)(b * SS + m) * HIDN) + h * HDD + n;
            *(float4*)p = v0; *(float4*)(p + 4) = v1;
        }
    }
}

// ---------------------------------------------------------------------------
// RoPE (in place). x layout: (B, nh, S, HD). One thread per (b,h,s,i<128).
// ---------------------------------------------------------------------------
__global__ void rope_k(float* __restrict__ x, const int* __restrict__ pos_ids, int nh)
{
    int idx = blockIdx.x * blockDim.x + threadIdx.x;
    int total = BB * nh * SS * (HDD / 2);
    if (idx >= total) return;
    int i  = idx & 127;
    int r  = idx >> 7;
    int s  = r & (SS - 1);
    int r2 = r >> 11;
    int h  = r2 % nh;
    int b  = r2 / nh;

    int pos = pos_ids[b * SS + s];
    float inv = expf(-logf(10000.0f) * (float)(2 * i) / 256.0f);
    float ang = (float)pos * inv;
    float c = cosf(ang), sn = sinf(ang);

    float* p = x + (((size_t)(b * nh + h) * SS + s) * HDD);
    float x1 = p[i], x2 = p[i + 128];
    p[i]       = x1 * c - x2 * sn;
    p[i + 128] = x2 * c + x1 * sn;
}

// ---------------------------------------------------------------------------
// Causal softmax, one block (256 thr) per row of 2048. Writes exact zeros
// for t > s (equivalent to softmax with -1e9 mask in fp32: expf underflows).
// Never reads t > s (score tiles there were skipped / are poison).
// ---------------------------------------------------------------------------
__global__ __launch_bounds__(256) void softmax_k(float* __restrict__ attn)
{
    int row = blockIdx.x;            // over B*H*S
    int s = row & (SS - 1);
    float* p = attn + (size_t)row * SS;
    int nv = s + 1;
    int tid = threadIdx.x;

    float vals[8];
    float mx = -3.4e38f;
    #pragma unroll
    for (int j = 0; j < 8; j++) {
        int t = tid + j * 256;
        vals[j] = (t < nv) ? p[t] : -3.4e38f;
        mx = fmaxf(mx, vals[j]);
    }
    __shared__ float red[8];
    #pragma unroll
    for (int off = 16; off; off >>= 1) mx = fmaxf(mx, __shfl_xor_sync(0xffffffffu, mx, off));
    if ((tid & 31) == 0) red[tid >> 5] = mx;
    __syncthreads();
    mx = red[0];
    #pragma unroll
    for (int w = 1; w < 8; w++) mx = fmaxf(mx, red[w]);

    float sum = 0.f;
    #pragma unroll
    for (int j = 0; j < 8; j++) sum += expf(vals[j] - mx);  // invalid -> expf(-inf)=0
    #pragma unroll
    for (int off = 16; off; off >>= 1) sum += __shfl_xor_sync(0xffffffffu, sum, off);
    __syncthreads();
    if ((tid & 31) == 0) red[tid >> 5] = sum;
    __syncthreads();
    sum = red[0];
    #pragma unroll
    for (int w = 1; w < 8; w++) sum += red[w];
    float inv = 1.0f / sum;

    #pragma unroll
    for (int j = 0; j < 8; j++) {
        int t = tid + j * 256;
        p[t] = (t < nv) ? expf(vals[j] - mx) * inv : 0.0f;
    }
}

// ---------------------------------------------------------------------------
extern "C" void kernel_launch(void* const* d_in, const int* in_sizes, int n_in,
                              void* d_out, int out_size)
{
    const float* hid = (const float*)d_in[0];
    // d_in[1] = attention_mask: unused (causality handled exactly in softmax)
    const int*   pos = (const int*)d_in[2];
    const float* Wq  = (const float*)d_in[3];
    const float* Wk  = (const float*)d_in[4];
    const float* Wv  = (const float*)d_in[5];
    const float* Wo  = (const float*)d_in[6];

    float* out0 = (float*)d_out;                       // (B,S,HID)
    float* attn = out0 + (size_t)BB * SS * HIDN;       // (B,H,S,S)

    float *q, *k, *v, *ctx;
    cudaGetSymbolAddress((void**)&q,   g_q);
    cudaGetSymbolAddress((void**)&k,   g_k);
    cudaGetSymbolAddress((void**)&v,   g_v);
    cudaGetSymbolAddress((void**)&ctx, g_ctx);

    const int M = BB * SS;  // 4096

    // k, v projections (plain NN GEMMs, output already in (B,S,HD) layout)
    gemm_k<0><<<dim3(HDD / 128, M / 128), 256>>>(hid, Wk, k, M, HDD, HIDN);
    gemm_k<0><<<dim3(HDD / 128, M / 128), 256>>>(hid, Wv, v, M, HDD, HIDN);
    // q projection with scatter to (B,H,S,HD)
    gemm_k<1><<<dim3(HIDN / 128, M / 128), 256>>>(hid, Wq, q, M, HIDN, HIDN);

    // RoPE in place
    rope_k<<<(BB * HH * SS * (HDD / 2) + 255) / 256, 256>>>(q, pos, HH);
    rope_k<<<(BB * 1  * SS * (HDD / 2) + 255) / 256, 256>>>(k, pos, 1);

    // scores = scale * q @ k^T (causal tiles skipped), batched over (b,h)
    gemm_k<2><<<dim3(SS / 128, SS / 128, BB * HH), 256>>>(q, k, attn, SS, SS, HDD);

    // causal softmax (writes exact zeros for t > s)
    softmax_k<<<BB * HH * SS, 256>>>(attn);

    // ctx = attn @ v (K truncated per tile), scatter to (B,S,H*HD)
    gemm_k<3><<<dim3(HDD / 128, SS / 128, BB * HH), 256>>>(attn, v, ctx, SS, HDD, SS);

    // out = ctx @ Wo
    gemm_k<0><<<dim3(HIDN / 128, M / 128), 256>>>(ctx, Wo, out0, M, HIDN, HIDN);
}

// round 2
// speedup vs baseline: 2.6940x; 2.6940x over previous
#include <cuda_runtime.h>
#include <math.h>
#include <stdint.h>

// Problem constants (fixed shapes)
#define BB   2
#define SS   2048
#define HIDN 2048
#define HH   8
#define HDD  256

// Scratch (allocation-free rule: __device__ globals)
__device__ float g_q[(size_t)BB*HH*SS*HDD];   // (B,H,S,HD)
__device__ float g_k[(size_t)BB*SS*HDD];      // (B,S,HD)
__device__ float g_v[(size_t)BB*SS*HDD];      // (B,S,HD)
__device__ float g_ctx[(size_t)BB*SS*HIDN];   // (B,S,H*HD)

__device__ __forceinline__ float tf32r(float x) {
    uint32_t u;
    asm("cvt.rna.tf32.f32 %0, %1;" : "=r"(u) : "f"(x));
    return __uint_as_float(u);
}

__device__ __forceinline__ void mma_tf32(float c[4], const uint32_t a[4], const uint32_t b[2]) {
    asm volatile(
        "mma.sync.aligned.m16n8k8.row.col.f32.tf32.tf32.f32 "
        "{%0,%1,%2,%3}, {%4,%5,%6,%7}, {%8,%9}, {%0,%1,%2,%3};"
        : "+f"(c[0]), "+f"(c[1]), "+f"(c[2]), "+f"(c[3])
        : "r"(a[0]), "r"(a[1]), "r"(a[2]), "r"(a[3]), "r"(b[0]), "r"(b[1]));
}

// ---------------------------------------------------------------------------
// TF32 tensor-core GEMM. 128x128 block tile, K-tile 16, 256 threads (8 warps
// in 2x4), warp tile 64x32 via m16n8k8. Register-prefetch pipeline.
// MODE 0: C = A@B (row-major)                 [k,v proj; ctx@Wo]
// MODE 1: q proj, scatter to (B,H,S,HD)
// MODE 2: scores = scale * q @ k^T, batched z=(b,h), causal block skip
// MODE 3: ctx = attn @ v, batched z=(b,h), K truncated at m0+128, scatter
// ---------------------------------------------------------------------------
template<int MODE>
__global__ __launch_bounds__(256) void tgemm(const float* __restrict__ Ag,
                                             const float* __restrict__ Bg,
                                             float* __restrict__ Cg,
                                             int M, int N, int K)
{
    __shared__ float As[16][136];   // [k][m], pad 8 -> conflict-free frags
    __shared__ float Bs[16][136];   // [k][n]

    const int tid  = threadIdx.x;
    const int warp = tid >> 5, lane = tid & 31;
    const int lr   = lane >> 2;     // 0..7
    const int lc   = lane & 3;      // 0..3
    const int mw   = (warp >> 2) * 64;   // warp m offset in tile
    const int nw   = (warp & 3) * 32;    // warp n offset in tile
    const int m0   = blockIdx.y * 128;
    const int n0   = blockIdx.x * 128;
    const int z    = blockIdx.z;

    if (MODE == 2 && blockIdx.x > blockIdx.y) return;  // fully-masked tile

    const float* A;
    const float* B;
    int lda, ldb, Kloop;
    if (MODE == 2) {
        A = Ag + (size_t)z * SS * HDD;        lda = HDD;
        B = Bg + (size_t)(z >> 3) * SS * HDD; ldb = HDD;   // k, NT access
        Kloop = HDD;
    } else if (MODE == 3) {
        A = Ag + (size_t)z * SS * SS;         lda = SS;
        B = Bg + (size_t)(z >> 3) * SS * HDD; ldb = HDD;
        Kloop = m0 + 128;                     // attn[t>s]==0 exactly
    } else {
        A = Ag; lda = K; B = Bg; ldb = N; Kloop = K;
    }

    // loader indices
    const int a_r  = tid >> 2;        // 0..63 (+64 for second half)
    const int a_c  = (tid & 3) * 4;   // k offset within tile
    const int b_kr = tid >> 5;        // 0..7 (+8)  (NN B load)
    const int b_c  = (tid & 31) * 4;  // n offset

    float4 pa[2], pb[2];

    auto loadG = [&](int k0) {
        #pragma unroll
        for (int i = 0; i < 2; i++)
            pa[i] = *(const float4*)&A[(size_t)(m0 + a_r + i * 64) * lda + k0 + a_c];
        if (MODE == 2) {
            #pragma unroll
            for (int i = 0; i < 2; i++)
                pb[i] = *(const float4*)&B[(size_t)(n0 + a_r + i * 64) * ldb + k0 + a_c];
        } else {
            #pragma unroll
            for (int i = 0; i < 2; i++)
                pb[i] = *(const float4*)&B[(size_t)(k0 + b_kr + i * 8) * ldb + n0 + b_c];
        }
    };

    auto storeS = [&]() {
        #pragma unroll
        for (int i = 0; i < 2; i++) {
            int r = a_r + i * 64;
            As[a_c + 0][r] = tf32r(pa[i].x);
            As[a_c + 1][r] = tf32r(pa[i].y);
            As[a_c + 2][r] = tf32r(pa[i].z);
            As[a_c + 3][r] = tf32r(pa[i].w);
        }
        if (MODE == 2) {
            #pragma unroll
            for (int i = 0; i < 2; i++) {
                int r = a_r + i * 64;
                Bs[a_c + 0][r] = tf32r(pb[i].x);
                Bs[a_c + 1][r] = tf32r(pb[i].y);
                Bs[a_c + 2][r] = tf32r(pb[i].z);
                Bs[a_c + 3][r] = tf32r(pb[i].w);
            }
        } else {
            #pragma unroll
            for (int i = 0; i < 2; i++) {
                float4 t;
                t.x = tf32r(pb[i].x); t.y = tf32r(pb[i].y);
                t.z = tf32r(pb[i].z); t.w = tf32r(pb[i].w);
                *(float4*)&Bs[b_kr + i * 8][b_c] = t;
            }
        }
    };

    float acc[4][4][4];
    #pragma unroll
    for (int i = 0; i < 4; i++)
        #pragma unroll
        for (int j = 0; j < 4; j++)
            #pragma unroll
            for (int r = 0; r < 4; r++) acc[i][j][r] = 0.f;

    loadG(0);
    for (int k0 = 0; k0 < Kloop; k0 += 16) {
        storeS();
        __syncthreads();
        if (k0 + 16 < Kloop) loadG(k0 + 16);

        #pragma unroll
        for (int ks = 0; ks < 16; ks += 8) {
            uint32_t af[4][4], bf[4][2];
            #pragma unroll
            for (int i = 0; i < 4; i++) {
                int m = mw + i * 16 + lr;
                af[i][0] = __float_as_uint(As[ks + lc][m]);
                af[i][1] = __float_as_uint(As[ks + lc][m + 8]);
                af[i][2] = __float_as_uint(As[ks + lc + 4][m]);
                af[i][3] = __float_as_uint(As[ks + lc + 4][m + 8]);
            }
            #pragma unroll
            for (int j = 0; j < 4; j++) {
                int n = nw + j * 8 + lr;
                bf[j][0] = __float_as_uint(Bs[ks + lc][n]);
                bf[j][1] = __float_as_uint(Bs[ks + lc + 4][n]);
            }
            #pragma unroll
            for (int i = 0; i < 4; i++)
                #pragma unroll
                for (int j = 0; j < 4; j++)
                    mma_tf32(acc[i][j], af[i], bf[j]);
        }
        __syncthreads();
    }

    // epilogue: c0,c1 at (m, n..n+1); c2,c3 at (m+8, n..n+1)
    #pragma unroll
    for (int i = 0; i < 4; i++) {
        #pragma unroll
        for (int j = 0; j < 4; j++) {
            int m = m0 + mw + i * 16 + lr;
            int n = n0 + nw + j * 8 + 2 * lc;
            float2 v0 = make_float2(acc[i][j][0], acc[i][j][1]);
            float2 v1 = make_float2(acc[i][j][2], acc[i][j][3]);
            if (MODE == 0) {
                *(float2*)&Cg[(size_t)m * N + n]       = v0;
                *(float2*)&Cg[(size_t)(m + 8) * N + n] = v1;
            } else if (MODE == 1) {
                int b = m >> 11, h = n >> 8, d = n & (HDD - 1);
                size_t base = ((size_t)(b * HH + h) * SS) * HDD + d;
                *(float2*)&Cg[base + (size_t)(m & (SS - 1)) * HDD]       = v0;
                *(float2*)&Cg[base + (size_t)((m + 8) & (SS - 1)) * HDD] = v1;
            } else if (MODE == 2) {
                const float sc = 0.0625f;  // HD^-0.5
                v0.x *= sc; v0.y *= sc; v1.x *= sc; v1.y *= sc;
                float* p = Cg + (size_t)z * SS * SS;
                *(float2*)&p[(size_t)m * SS + n]       = v0;
                *(float2*)&p[(size_t)(m + 8) * SS + n] = v1;
            } else {  // MODE 3
                int b = z >> 3, h = z & 7;
                float* p = Cg + (size_t)b * SS * HIDN + h * HDD + n;
                *(float2*)&p[(size_t)m * HIDN]       = v0;
                *(float2*)&p[(size_t)(m + 8) * HIDN] = v1;
            }
        }
    }
}

// ---------------------------------------------------------------------------
// RoPE (in place). x layout: (B, nh, S, HD). One thread per (b,h,s,i<128).
// ---------------------------------------------------------------------------
__global__ void rope_k(float* __restrict__ x, const int* __restrict__ pos_ids, int nh)
{
    int idx = blockIdx.x * blockDim.x + threadIdx.x;
    int total = BB * nh * SS * (HDD / 2);
    if (idx >= total) return;
    int i  = idx & 127;
    int r  = idx >> 7;
    int s  = r & (SS - 1);
    int r2 = r >> 11;
    int h  = r2 % nh;
    int b  = r2 / nh;

    int pos = pos_ids[b * SS + s];
    float inv = expf(-logf(10000.0f) * (float)(2 * i) / 256.0f);
    float ang = (float)pos * inv;
    float c = cosf(ang), sn = sinf(ang);

    float* p = x + (((size_t)(b * nh + h) * SS + s) * HDD);
    float x1 = p[i], x2 = p[i + 128];
    p[i]       = x1 * c - x2 * sn;
    p[i + 128] = x2 * c + x1 * sn;
}

// ---------------------------------------------------------------------------
// Causal softmax, one block (256 thr) per row of 2048. Writes exact zeros
// for t > s.
// ---------------------------------------------------------------------------
__global__ __launch_bounds__(256) void softmax_k(float* __restrict__ attn)
{
    int row = blockIdx.x;            // over B*H*S
    int s = row & (SS - 1);
    float* p = attn + (size_t)row * SS;
    int nv = s + 1;
    int tid = threadIdx.x;

    float vals[8];
    float mx = -3.4e38f;
    #pragma unroll
    for (int j = 0; j < 8; j++) {
        int t = tid + j * 256;
        vals[j] = (t < nv) ? p[t] : -3.4e38f;
        mx = fmaxf(mx, vals[j]);
    }
    __shared__ float red[8];
    #pragma unroll
    for (int off = 16; off; off >>= 1) mx = fmaxf(mx, __shfl_xor_sync(0xffffffffu, mx, off));
    if ((tid & 31) == 0) red[tid >> 5] = mx;
    __syncthreads();
    mx = red[0];
    #pragma unroll
    for (int w = 1; w < 8; w++) mx = fmaxf(mx, red[w]);

    float sum = 0.f;
    #pragma unroll
    for (int j = 0; j < 8; j++) sum += expf(vals[j] - mx);
    #pragma unroll
    for (int off = 16; off; off >>= 1) sum += __shfl_xor_sync(0xffffffffu, sum, off);
    __syncthreads();
    if ((tid & 31) == 0) red[tid >> 5] = sum;
    __syncthreads();
    sum = red[0];
    #pragma unroll
    for (int w = 1; w < 8; w++) sum += red[w];
    float inv = 1.0f / sum;

    #pragma unroll
    for (int j = 0; j < 8; j++) {
        int t = tid + j * 256;
        p[t] = (t < nv) ? expf(vals[j] - mx) * inv : 0.0f;
    }
}

// ---------------------------------------------------------------------------
extern "C" void kernel_launch(void* const* d_in, const int* in_sizes, int n_in,
                              void* d_out, int out_size)
{
    const float* hid = (const float*)d_in[0];
    // d_in[1] = attention_mask: unused (causality handled exactly in softmax)
    const int*   pos = (const int*)d_in[2];
    const float* Wq  = (const float*)d_in[3];
    const float* Wk  = (const float*)d_in[4];
    const float* Wv  = (const float*)d_in[5];
    const float* Wo  = (const float*)d_in[6];

    float* out0 = (float*)d_out;                       // (B,S,HID)
    float* attn = out0 + (size_t)BB * SS * HIDN;       // (B,H,S,S)

    float *q, *k, *v, *ctx;
    cudaGetSymbolAddress((void**)&q,   g_q);
    cudaGetSymbolAddress((void**)&k,   g_k);
    cudaGetSymbolAddress((void**)&v,   g_v);
    cudaGetSymbolAddress((void**)&ctx, g_ctx);

    const int M = BB * SS;  // 4096

    // k, v projections (plain NN GEMMs, output already in (B,S,HD) layout)
    tgemm<0><<<dim3(HDD / 128, M / 128), 256>>>(hid, Wk, k, M, HDD, HIDN);
    tgemm<0><<<dim3(HDD / 128, M / 128), 256>>>(hid, Wv, v, M, HDD, HIDN);
    // q projection with scatter to (B,H,S,HD)
    tgemm<1><<<dim3(HIDN / 128, M / 128), 256>>>(hid, Wq, q, M, HIDN, HIDN);

    // RoPE in place
    rope_k<<<(BB * HH * SS * (HDD / 2) + 255) / 256, 256>>>(q, pos, HH);
    rope_k<<<(BB * 1  * SS * (HDD / 2) + 255) / 256, 256>>>(k, pos, 1);

    // scores = scale * q @ k^T (causal tiles skipped), batched over (b,h)
    tgemm<2><<<dim3(SS / 128, SS / 128, BB * HH), 256>>>(q, k, attn, SS, SS, HDD);

    // causal softmax (writes exact zeros for t > s)
    softmax_k<<<BB * HH * SS, 256>>>(attn);

    // ctx = attn @ v (K truncated per tile), scatter to (B,S,H*HD)
    tgemm<3><<<dim3(HDD / 128, SS / 128, BB * HH), 256>>>(attn, v, ctx, SS, HDD, SS);

    // out = ctx @ Wo
    tgemm<0><<<dim3(HIDN / 128, M / 128), 256>>>(ctx, Wo, out0, M, HIDN, HIDN);
}

// round 5
// speedup vs baseline: 4.3113x; 1.6003x over previous
#include <cuda_runtime.h>
#include <math.h>
#include <stdint.h>

#define BB   2
#define SS   2048
#define HIDN 2048
#define HH   8
#define HDD  256

// ---------------- scratch (__device__ globals; no allocs allowed) ----------
__device__ float g_hid[(size_t)BB*SS*HIDN];     // tf32-rounded copy of hidden
__device__ float g_q  [(size_t)BB*HH*SS*HDD];   // (B,H,S,HD)
__device__ float g_k  [(size_t)BB*SS*HDD];      // (B,S,HD)
__device__ float g_v  [(size_t)BB*SS*HDD];      // (B,S,HD)
__device__ float g_vT [(size_t)BB*HDD*SS];      // (B,HD,S)
__device__ float g_ctx[(size_t)BB*SS*HIDN];     // (B,S,H*HD)
__device__ float g_wqT[(size_t)HIDN*HIDN];      // Wq^T  [n][k]
__device__ float g_wkT[(size_t)HDD*HIDN];       // Wk^T
__device__ float g_wvT[(size_t)HDD*HIDN];       // Wv^T
__device__ float g_woT[(size_t)HIDN*HIDN];      // Wo^T

// ---------------- helpers ---------------------------------------------------
__device__ __forceinline__ float tf32r(float x) {
    uint32_t u;
    asm("cvt.rna.tf32.f32 %0, %1;" : "=r"(u) : "f"(x));
    return __uint_as_float(u);
}

__device__ __forceinline__ uint32_t smem_u32(const void* p) {
    uint32_t a;
    asm("{ .reg .u64 t; cvta.to.shared.u64 t, %1; cvt.u32.u64 %0, t; }" : "=r"(a) : "l"(p));
    return a;
}

__device__ __forceinline__ void mma_tf32(float c[4], const uint32_t a[4], const uint32_t b[2]) {
    asm volatile(
        "mma.sync.aligned.m16n8k8.row.col.f32.tf32.tf32.f32 "
        "{%0,%1,%2,%3}, {%4,%5,%6,%7}, {%8,%9}, {%0,%1,%2,%3};"
        : "+f"(c[0]), "+f"(c[1]), "+f"(c[2]), "+f"(c[3])
        : "r"(a[0]), "r"(a[1]), "r"(a[2]), "r"(a[3]), "r"(b[0]), "r"(b[1]));
}

#define CP_ASYNC16(dst, src) \
    asm volatile("cp.async.cg.shared.global [%0], [%1], 16;" :: "r"(dst), "l"(src))
#define CP_COMMIT()  asm volatile("cp.async.commit_group;" ::: "memory")
#define CP_WAIT2()   asm volatile("cp.async.wait_group 2;" ::: "memory")

// ---------------- pipelined tf32 mma.sync GEMM ------------------------------
// 128x128 block tile, K-tile 32, 3-stage cp.async ring, 8 warps (2x4),
// warp tile 64x32 via m16n8k8. All operands K-major: A[m][k], B[n][k].
// Rows stored as 128B with 16B-chunk XOR swizzle (chunk ^ (row&7)).
// MODE 0: ctx @ WoT -> out            (no rounding of C)
// MODE 1: hid @ WqT -> q scatter      (round C)
// MODE 2: q @ k^T * scale -> attn     (no rounding; causal block skip)
// MODE 3: attn @ vT -> ctx scatter    (round C; K truncated at m0+128)
// MODE 4: hid @ {WkT,WvT} -> {k,v}    (round C; z selects pair)
#define NST      3
#define STG      16384
#define SMEM_TOT (2*NST*STG)

template<int MODE>
__global__ void __launch_bounds__(256, 2)
pgemm(const float* __restrict__ Ag, const float* __restrict__ Bg,
      const float* __restrict__ Bg2, float* __restrict__ Cg,
      float* __restrict__ Cg2)
{
    extern __shared__ char smem[];
    const int tid = threadIdx.x;
    const int m0  = blockIdx.y * 128;
    const int n0  = blockIdx.x * 128;
    const int z   = blockIdx.z;

    if (MODE == 2 && blockIdx.x > blockIdx.y) return;   // fully-masked tile

    const float* A; const float* B; float* C;
    int lda, ldb, nTiles;
    if (MODE == 2) {
        A = Ag + (size_t)z * SS * HDD;        lda = HDD;
        B = Bg + (size_t)(z >> 3) * SS * HDD; ldb = HDD;
        C = Cg; nTiles = HDD / 32;                      // 8
    } else if (MODE == 3) {
        A = Ag + (size_t)z * SS * SS;         lda = SS;
        B = Bg + (size_t)(z >> 3) * HDD * SS; ldb = SS;
        C = Cg; nTiles = (m0 + 128) / 32;               // 4..64
    } else if (MODE == 4) {
        A = Ag; lda = HIDN;
        B = z ? Bg2 : Bg; ldb = HIDN;
        C = z ? Cg2 : Cg; nTiles = HIDN / 32;           // 64
    } else {
        A = Ag; lda = HIDN; B = Bg; ldb = HIDN; C = Cg; nTiles = HIDN / 32;
    }

    const uint32_t sbA = smem_u32(smem);
    const uint32_t sbB = sbA + NST * STG;

    // ---- async loader mapping: 8 chunks x 32 rows x 4 waves per matrix ----
    const int c  = tid & 7;      // 16B chunk in row
    const int r0 = tid >> 3;     // 0..31

    auto load_tile = [&](int t, int buf) {
        const int k0 = t * 32;
        const uint32_t dA = sbA + buf * STG;
        const uint32_t dB = sbB + buf * STG;
        #pragma unroll
        for (int w = 0; w < 4; w++) {
            int r = r0 + 32 * w;
            uint32_t off = (uint32_t)(r * 128 + ((c ^ (r & 7)) << 4));
            CP_ASYNC16(dA + off, A + (size_t)(m0 + r) * lda + k0 + c * 4);
            CP_ASYNC16(dB + off, B + (size_t)(n0 + r) * ldb + k0 + c * 4);
        }
        CP_COMMIT();
    };

    // ---- fragment addressing (base offsets precomputed; per-k8 XOR only) --
    const int warp = tid >> 5, lane = tid & 31;
    const int lr = lane >> 2, lc = lane & 3;
    const int mw = (warp >> 2) * 64;
    const int nw = (warp & 3) * 32;

    uint32_t aoff[4], boff[4];
    #pragma unroll
    for (int i = 0; i < 4; i++) aoff[i] = (uint32_t)((mw + i * 16 + lr) * 128 + lc * 4);
    #pragma unroll
    for (int j = 0; j < 4; j++) boff[j] = (uint32_t)((nw + j * 8 + lr) * 128 + lc * 4);

    float acc[4][4][4];
    #pragma unroll
    for (int i = 0; i < 4; i++)
        #pragma unroll
        for (int j = 0; j < 4; j++)
            #pragma unroll
            for (int r = 0; r < 4; r++) acc[i][j][r] = 0.f;

    auto compute = [&](int buf) {
        const char* cA = smem + buf * STG;
        const char* cB = smem + NST * STG + buf * STG;
        #pragma unroll
        for (int k8 = 0; k8 < 4; k8++) {
            const uint32_t s0 = (uint32_t)(((2 * k8)     ^ lr) << 4);
            const uint32_t s1 = (uint32_t)(((2 * k8 + 1) ^ lr) << 4);
            uint32_t af[4][4], bf[4][2];
            #pragma unroll
            for (int i = 0; i < 4; i++) {
                af[i][0] = *(const uint32_t*)(cA + aoff[i] + s0);
                af[i][1] = *(const uint32_t*)(cA + aoff[i] + 1024 + s0);
                af[i][2] = *(const uint32_t*)(cA + aoff[i] + s1);
                af[i][3] = *(const uint32_t*)(cA + aoff[i] + 1024 + s1);
            }
            #pragma unroll
            for (int j = 0; j < 4; j++) {
                bf[j][0] = *(const uint32_t*)(cB + boff[j] + s0);
                bf[j][1] = *(const uint32_t*)(cB + boff[j] + s1);
            }
            #pragma unroll
            for (int i = 0; i < 4; i++)
                #pragma unroll
                for (int j = 0; j < 4; j++)
                    mma_tf32(acc[i][j], af[i], bf[j]);
        }
    };

    // ---- 3-stage pipeline ----
    load_tile(0, 0); load_tile(1, 1); load_tile(2, 2);
    for (int t = 0; t < nTiles; t++) {
        const int b = t % NST;
        CP_WAIT2();
        __syncthreads();
        compute(b);
        __syncthreads();
        if (t + NST < nTiles) load_tile(t + NST, b);
        else                  CP_COMMIT();   // empty group keeps wait_group math exact
    }

    // ---- epilogue ----
    #pragma unroll
    for (int i = 0; i < 4; i++) {
        #pragma unroll
        for (int j = 0; j < 4; j++) {
            int m = m0 + mw + i * 16 + lr;
            int n = n0 + nw + j * 8 + 2 * lc;
            float2 v0 = make_float2(acc[i][j][0], acc[i][j][1]);
            float2 v1 = make_float2(acc[i][j][2], acc[i][j][3]);
            if (MODE == 1 || MODE == 3 || MODE == 4) {
                v0.x = tf32r(v0.x); v0.y = tf32r(v0.y);
                v1.x = tf32r(v1.x); v1.y = tf32r(v1.y);
            }
            if (MODE == 0) {
                *(float2*)&Cg[(size_t)m * HIDN + n]       = v0;
                *(float2*)&Cg[(size_t)(m + 8) * HIDN + n] = v1;
            } else if (MODE == 1) {
                int bb = m >> 11, h = n >> 8, d = n & (HDD - 1);
                size_t base = ((size_t)(bb * HH + h) * SS) * HDD + d;
                *(float2*)&Cg[base + (size_t)(m & (SS - 1)) * HDD]       = v0;
                *(float2*)&Cg[base + (size_t)((m + 8) & (SS - 1)) * HDD] = v1;
            } else if (MODE == 2) {
                const float sc = 0.0625f;   // HD^-0.5
                v0.x *= sc; v0.y *= sc; v1.x *= sc; v1.y *= sc;
                float* p = Cg + (size_t)z * SS * SS;
                *(float2*)&p[(size_t)m * SS + n]       = v0;
                *(float2*)&p[(size_t)(m + 8) * SS + n] = v1;
            } else if (MODE == 3) {
                int bb = z >> 3, h = z & 7;
                float* p = C + (size_t)bb * SS * HIDN + h * HDD + n;
                *(float2*)&p[(size_t)m * HIDN]       = v0;
                *(float2*)&p[(size_t)(m + 8) * HIDN] = v1;
            } else {  // MODE 4
                *(float2*)&C[(size_t)m * HDD + n]       = v0;
                *(float2*)&C[(size_t)(m + 8) * HDD + n] = v1;
            }
        }
    }
}

// ---------------- transpose (optionally rounding to tf32) -------------------
template<int ROUND>
__global__ void transpose_k(const float* __restrict__ src, float* __restrict__ dst,
                            int R, int C)
{
    __shared__ float t[32][33];
    src += (size_t)blockIdx.z * R * C;
    dst += (size_t)blockIdx.z * R * C;
    int c0 = blockIdx.x * 32, rr0 = blockIdx.y * 32;
    int tx = threadIdx.x, ty = threadIdx.y;
    #pragma unroll
    for (int i = 0; i < 4; i++)
        t[ty + 8 * i][tx] = src[(size_t)(rr0 + ty + 8 * i) * C + c0 + tx];
    __syncthreads();
    #pragma unroll
    for (int i = 0; i < 4; i++) {
        float v = t[tx][ty + 8 * i];
        dst[(size_t)(c0 + ty + 8 * i) * R + rr0 + tx] = ROUND ? tf32r(v) : v;
    }
}

// ---------------- tf32 round-copy -------------------------------------------
__global__ void roundcopy_k(const float* __restrict__ src, float* __restrict__ dst, int n4)
{
    int i = blockIdx.x * blockDim.x + threadIdx.x;
    if (i >= n4) return;
    float4 v = ((const float4*)src)[i];
    v.x = tf32r(v.x); v.y = tf32r(v.y); v.z = tf32r(v.z); v.w = tf32r(v.w);
    ((float4*)dst)[i] = v;
}

// ---------------- RoPE (in place, outputs re-rounded to tf32) ---------------
__global__ void rope_k(float* __restrict__ x, const int* __restrict__ pos_ids, int nh)
{
    int idx = blockIdx.x * blockDim.x + threadIdx.x;
    int total = BB * nh * SS * (HDD / 2);
    if (idx >= total) return;
    int i  = idx & 127;
    int r  = idx >> 7;
    int s  = r & (SS - 1);
    int r2 = r >> 11;
    int h  = r2 % nh;
    int b  = r2 / nh;

    int pos = pos_ids[b * SS + s];
    float inv = expf(-logf(10000.0f) * (float)(2 * i) / 256.0f);
    float ang = (float)pos * inv;
    float cs = cosf(ang), sn = sinf(ang);

    float* p = x + (((size_t)(b * nh + h) * SS + s) * HDD);
    float x1 = p[i], x2 = p[i + 128];
    p[i]       = tf32r(x1 * cs - x2 * sn);
    p[i + 128] = tf32r(x2 * cs + x1 * sn);
}

// ---------------- causal softmax (tf32-rounded output) ----------------------
__global__ __launch_bounds__(256) void softmax_k(float* __restrict__ attn)
{
    int row = blockIdx.x;
    int s = row & (SS - 1);
    float* p = attn + (size_t)row * SS;
    int nv = s + 1;
    int tid = threadIdx.x;

    float vals[8];
    float mx = -3.4e38f;
    #pragma unroll
    for (int j = 0; j < 8; j++) {
        int t = tid + j * 256;
        vals[j] = (t < nv) ? p[t] : -3.4e38f;
        mx = fmaxf(mx, vals[j]);
    }
    __shared__ float red[8];
    #pragma unroll
    for (int off = 16; off; off >>= 1) mx = fmaxf(mx, __shfl_xor_sync(0xffffffffu, mx, off));
    if ((tid & 31) == 0) red[tid >> 5] = mx;
    __syncthreads();
    mx = red[0];
    #pragma unroll
    for (int w = 1; w < 8; w++) mx = fmaxf(mx, red[w]);

    float sum = 0.f;
    #pragma unroll
    for (int j = 0; j < 8; j++) sum += expf(vals[j] - mx);
    #pragma unroll
    for (int off = 16; off; off >>= 1) sum += __shfl_xor_sync(0xffffffffu, sum, off);
    __syncthreads();
    if ((tid & 31) == 0) red[tid >> 5] = sum;
    __syncthreads();
    sum = red[0];
    #pragma unroll
    for (int w = 1; w < 8; w++) sum += red[w];
    float inv = 1.0f / sum;

    #pragma unroll
    for (int j = 0; j < 8; j++) {
        int t = tid + j * 256;
        p[t] = (t < nv) ? tf32r(expf(vals[j] - mx) * inv) : 0.0f;
    }
}

// ---------------------------------------------------------------------------
extern "C" void kernel_launch(void* const* d_in, const int* in_sizes, int n_in,
                              void* d_out, int out_size)
{
    const float* hid = (const float*)d_in[0];
    const int*   pos = (const int*)d_in[2];
    const float* Wq  = (const float*)d_in[3];
    const float* Wk  = (const float*)d_in[4];
    const float* Wv  = (const float*)d_in[5];
    const float* Wo  = (const float*)d_in[6];

    float* out0 = (float*)d_out;                       // (B,S,HID)
    float* attn = out0 + (size_t)BB * SS * HIDN;       // (B,H,S,S)

    float *hidR, *q, *k, *v, *vT, *ctx, *wqT, *wkT, *wvT, *woT;
    cudaGetSymbolAddress((void**)&hidR, g_hid);
    cudaGetSymbolAddress((void**)&q,    g_q);
    cudaGetSymbolAddress((void**)&k,    g_k);
    cudaGetSymbolAddress((void**)&v,    g_v);
    cudaGetSymbolAddress((void**)&vT,   g_vT);
    cudaGetSymbolAddress((void**)&ctx,  g_ctx);
    cudaGetSymbolAddress((void**)&wqT,  g_wqT);
    cudaGetSymbolAddress((void**)&wkT,  g_wkT);
    cudaGetSymbolAddress((void**)&wvT,  g_wvT);
    cudaGetSymbolAddress((void**)&woT,  g_woT);

    cudaFuncSetAttribute(pgemm<0>, cudaFuncAttributeMaxDynamicSharedMemorySize, SMEM_TOT);
    cudaFuncSetAttribute(pgemm<1>, cudaFuncAttributeMaxDynamicSharedMemorySize, SMEM_TOT);
    cudaFuncSetAttribute(pgemm<2>, cudaFuncAttributeMaxDynamicSharedMemorySize, SMEM_TOT);
    cudaFuncSetAttribute(pgemm<3>, cudaFuncAttributeMaxDynamicSharedMemorySize, SMEM_TOT);
    cudaFuncSetAttribute(pgemm<4>, cudaFuncAttributeMaxDynamicSharedMemorySize, SMEM_TOT);

    // tf32-round hidden states; transpose (+round) weights
    int n4 = BB * SS * HIDN / 4;
    roundcopy_k<<<(n4 + 255) / 256, 256>>>(hid, hidR, n4);
    transpose_k<1><<<dim3(HIDN / 32, HIDN / 32, 1), dim3(32, 8)>>>(Wq, wqT, HIDN, HIDN);
    transpose_k<1><<<dim3(HDD  / 32, HIDN / 32, 1), dim3(32, 8)>>>(Wk, wkT, HIDN, HDD);
    transpose_k<1><<<dim3(HDD  / 32, HIDN / 32, 1), dim3(32, 8)>>>(Wv, wvT, HIDN, HDD);
    transpose_k<1><<<dim3(HIDN / 32, HIDN / 32, 1), dim3(32, 8)>>>(Wo, woT, HIDN, HIDN);

    // projections (k,v fused over grid.z; q with scatter)
    pgemm<4><<<dim3(HDD / 128, (BB * SS) / 128, 2), 256, SMEM_TOT>>>(hidR, wkT, wvT, k, v);
    pgemm<1><<<dim3(HIDN / 128, (BB * SS) / 128), 256, SMEM_TOT>>>(hidR, wqT, nullptr, q, nullptr);

    // RoPE (in place; outputs tf32-rounded)
    rope_k<<<(BB * HH * SS * (HDD / 2) + 255) / 256, 256>>>(q, pos, HH);
    rope_k<<<(BB * 1  * SS * (HDD / 2) + 255) / 256, 256>>>(k, pos, 1);

    // v^T per batch (values already tf32-rounded)
    transpose_k<0><<<dim3(HDD / 32, SS / 32, BB), dim3(32, 8)>>>(v, vT, SS, HDD);

    // scores = scale * q @ k^T  (causal block skip)
    pgemm<2><<<dim3(SS / 128, SS / 128, BB * HH), 256, SMEM_TOT>>>(q, k, nullptr, attn, nullptr);

    // causal softmax (exact zeros above diagonal; tf32-rounded probs)
    softmax_k<<<BB * HH * SS, 256>>>(attn);

    // ctx = attn @ v  (K truncated per row-block)
    pgemm<3><<<dim3(HDD / 128, SS / 128, BB * HH), 256, SMEM_TOT>>>(attn, vT, nullptr, ctx, nullptr);

    // out = ctx @ Wo
    pgemm<0><<<dim3(HIDN / 128, (BB * SS) / 128), 256, SMEM_TOT>>>(ctx, woT, nullptr, out0, nullptr);
}